// round 3
// baseline (speedup 1.0000x reference)
#include <cuda_runtime.h>
#include <cuda_bf16.h>
#include <math.h>

// ============================================================================
// quantizer: out = center[argmin_m |x - center[m]|]  (== W_hard; reference's
// (W_hard - W_soft) + W_soft == W_hard up to 1 ulp).
//
// R3: single fused kernel. Each CTA self-preps (shuffle rank-sort of the 16
// centers, 15 parallel bisections for the EXACT fp32 argmin crossovers, fill a
// 64KB byte-LUT in shared). LUT stores the final region index for pure cells
// (sentinel 0xFF for cells containing a crossover). Fast path per element:
//   FFMA -> F2I.rn -> clamp -> LDS.U8 -> SHFL(center, r)
// One warp-uniform vote per 8 elements; rare fallback does a 4-step SHFL
// binary search over the exact crossovers (multiplicity-safe).
// ============================================================================

#define LUT_SIZE 65536

__device__ __forceinline__ int qcode(float xv, float scale, float bias)
{
    unsigned code = __float2uint_rn(fmaf(xv, scale, bias)); // negatives -> 0
    return (int)umin(code, (unsigned)(LUT_SIZE - 1));
}

// robust resolve: r = #{k : cross[k] <= x} via 4-step warp-shfl binary search
// over the 15 sorted exact crossovers (cross[15] = +inf); then gather center.
__device__ __forceinline__ float qrobust(float xv, float crossv, float centv)
{
    int r = 0;
    #pragma unroll
    for (int s = 8; s >= 1; s >>= 1) {
        float thr = __shfl_sync(0xffffffffu, crossv, r + s - 1);
        r += (xv >= thr) ? s : 0;
    }
    return __shfl_sync(0xffffffffu, centv, r);
}

extern "C" __global__ void __launch_bounds__(1024, 2)
quant_fused_kernel(const float4* __restrict__ x,
                   const float* __restrict__ center,
                   float4* __restrict__ out, int n4)
{
    extern __shared__ unsigned char sblut[];      // 64 KB byte LUT
    __shared__ float s_c[16];                     // sorted centers
    __shared__ int   s_oi[16];                    // original indices (tie rule)
    __shared__ float s_cross[16];                 // exact crossovers, [15]=+inf
    __shared__ float s_scale, s_bias;

    const int tid  = threadIdx.x;
    const int lane = tid & 31;

    // ---- stage 1: rank-sort 16 centers (lanes 0..15 of warp 0) ----
    if (tid < 16) {
        float ci = center[tid];
        int rank = 0;
        #pragma unroll
        for (int j = 0; j < 16; j++) {
            float cj = __shfl_sync(0xffffu, ci, j);
            rank += (cj < ci || (cj == ci && j < tid)) ? 1 : 0;
        }
        s_c[rank]  = ci;
        s_oi[rank] = tid;
    }
    __syncthreads();

    // ---- stage 2: grid params + exact crossovers ----
    if (tid == 0) {
        float mid0  = 0.5f * (s_c[0]  + s_c[1]);
        float mid14 = 0.5f * (s_c[14] + s_c[15]);
        float span  = mid14 - mid0;
        if (!(span > 0.0f)) span = 1e-6f;
        float step = span / (float)(LUT_SIZE - 160);   // 80-cell margins
        float lo   = mid0 - 80.0f * step;
        s_scale = 1.0f / step;
        s_bias  = -lo / step;
    }
    if (tid < 16) {
        float cv;
        if (tid < 15) {
            // exact fp32 flip point of the reference's argmin decision for
            // the adjacent sorted pair (bracket [c_k, c_{k+1}], monotone
            // predicate, bisect to adjacent floats)
            float cl = s_c[tid], cr = s_c[tid + 1];
            int   ol = s_oi[tid], orr = s_oi[tid + 1];
            float a = cl, b = cr;
            for (int it = 0; it < 60; it++) {
                float m = 0.5f * (a + b);
                if (m <= a || m >= b) break;
                float dl = fabsf(m - cl), dr = fabsf(m - cr);
                bool pl = (dl < dr) || (dl == dr && ol < orr);
                if (pl) a = m; else b = m;
            }
            cv = b;                         // smallest x picking RIGHT center
        } else {
            cv = __int_as_float(0x7f800000);  // +inf sentinel
        }
        s_cross[tid] = cv;
    }
    __syncthreads();

    // ---- stage 3: fill 64KB byte LUT ----
    const float scale = s_scale, bias = s_bias;
    const float inv = 1.0f / scale;
    for (int i = tid; i < LUT_SIZE; i += 1024) {
        // conservative x-window of code i (rn 0.5 + fma rounding + margin)
        float xlo = ((float)i - 1.5f - bias) * inv;
        float xhi = ((float)i + 1.5f - bias) * inv;
        int below = 0, inwin = 0;
        #pragma unroll
        for (int k = 0; k < 15; k++) {
            float ck = s_cross[k];
            below += (ck < xlo) ? 1 : 0;
            inwin += (ck >= xlo && ck <= xhi) ? 1 : 0;
        }
        sblut[i] = inwin ? (unsigned char)0xFF : (unsigned char)below;
    }

    const float crossv = s_cross[lane & 15];   // per-lane register tables
    const float centv  = s_c[lane & 15];
    __syncthreads();

    // ---- main loop: warp-uniform bounds (shuffles/votes always full-warp) ----
    const int stride = gridDim.x * blockDim.x;
    int i  = blockIdx.x * blockDim.x + tid;
    int wb = i - lane;

    for (; wb + 31 + stride < n4; i += 2 * stride, wb += 2 * stride) {
        float4 a = x[i];
        float4 b = x[i + stride];

        int c0 = qcode(a.x, scale, bias), c1 = qcode(a.y, scale, bias);
        int c2 = qcode(a.z, scale, bias), c3 = qcode(a.w, scale, bias);
        int c4 = qcode(b.x, scale, bias), c5 = qcode(b.y, scale, bias);
        int c6 = qcode(b.z, scale, bias), c7 = qcode(b.w, scale, bias);

        int b0 = sblut[c0], b1 = sblut[c1], b2 = sblut[c2], b3 = sblut[c3];
        int b4 = sblut[c4], b5 = sblut[c5], b6 = sblut[c6], b7 = sblut[c7];

        int orall = ((b0 | b1) | (b2 | b3)) | ((b4 | b5) | (b6 | b7));
        float4 ra, rb;
        if (!__any_sync(0xffffffffu, orall >= 16)) {
            // fast path: region index is exact -> one shfl per element
            ra.x = __shfl_sync(0xffffffffu, centv, b0);
            ra.y = __shfl_sync(0xffffffffu, centv, b1);
            ra.z = __shfl_sync(0xffffffffu, centv, b2);
            ra.w = __shfl_sync(0xffffffffu, centv, b3);
            rb.x = __shfl_sync(0xffffffffu, centv, b4);
            rb.y = __shfl_sync(0xffffffffu, centv, b5);
            rb.z = __shfl_sync(0xffffffffu, centv, b6);
            rb.w = __shfl_sync(0xffffffffu, centv, b7);
        } else {
            // rare: some lane's cell contains a crossover -> exact search
            ra.x = qrobust(a.x, crossv, centv);
            ra.y = qrobust(a.y, crossv, centv);
            ra.z = qrobust(a.z, crossv, centv);
            ra.w = qrobust(a.w, crossv, centv);
            rb.x = qrobust(b.x, crossv, centv);
            rb.y = qrobust(b.y, crossv, centv);
            rb.z = qrobust(b.z, crossv, centv);
            rb.w = qrobust(b.w, crossv, centv);
        }
        out[i]          = ra;
        out[i + stride] = rb;
    }
    // tail: full-warp shuffles, predicated LDG/STG, robust path (few iters)
    for (; wb < n4; i += stride, wb += stride) {
        const bool v = (i < n4);
        float4 a = v ? x[i] : make_float4(0.f, 0.f, 0.f, 0.f);
        float4 r;
        r.x = qrobust(a.x, crossv, centv);
        r.y = qrobust(a.y, crossv, centv);
        r.z = qrobust(a.z, crossv, centv);
        r.w = qrobust(a.w, crossv, centv);
        if (v) out[i] = r;
    }
}

// ---------------------------------------------------------------------------
extern "C" void kernel_launch(void* const* d_in, const int* in_sizes, int n_in,
                              void* d_out, int out_size)
{
    const float* x      = (const float*)d_in[0];
    const float* center = (const float*)d_in[1];
    float*       out    = (float*)d_out;
    (void)n_in; (void)out_size;

    const int n  = in_sizes[0];
    const int n4 = n >> 2;

    // opt-in to 64 KB dynamic shared memory (idempotent, capture-safe)
    cudaFuncSetAttribute(quant_fused_kernel,
                         cudaFuncAttributeMaxDynamicSharedMemorySize, LUT_SIZE);

    const int threads = 1024;
    const int blocks  = 296;   // 2 CTAs/SM x 148 SMs
    quant_fused_kernel<<<blocks, threads, LUT_SIZE>>>(
        (const float4*)x, center, (float4*)out, n4);
}

// round 6
// speedup vs baseline: 1.8025x; 1.8025x over previous
#include <cuda_runtime.h>
#include <cuda_bf16.h>
#include <math.h>

// ============================================================================
// quantizer: out = center[argmin_m |x - center[m]|]  (== W_hard; reference's
// (W_hard - W_soft) + W_soft == W_hard up to 1 ulp).
//
// R4b: single fused kernel (prep + main). 8192-entry fp32 LUT in static shared
// memory stores the CENTER VALUE for pure cells, NaN sentinel for the ~45
// cells containing an argmin crossover. Main path per element:
//   FFMA -> F2I.rn (sat) -> clamp -> LDS.32  (no shuffles, no warp votes)
// NaN check amortized to one FSETP+BRA per float4 (sum trick); rare per-lane
// fixup counts exact crossovers from shared (divergence-safe, no shuffles).
// ============================================================================

#define LUT_N 8192

__device__ __forceinline__ unsigned qcode(float xv, float scale, float bias)
{
    unsigned code = __float2uint_rn(fmaf(xv, scale, bias)); // negatives -> 0
    return umin(code, (unsigned)(LUT_N - 1));
}

extern "C" __global__ void __launch_bounds__(1024, 2)
quant_fused_kernel(const float4* __restrict__ x,
                   const float* __restrict__ center,
                   float4* __restrict__ out, int n4)
{
    __shared__ float s_lut[LUT_N];   // 32 KB value LUT
    __shared__ float s_c[16];        // sorted centers
    __shared__ int   s_oi[16];       // original indices (argmin tie rule)
    __shared__ float s_cross[16];    // exact crossovers, [15] = +inf
    __shared__ float s_scale, s_bias;

    const int tid = threadIdx.x;

    // ---- prep 1: rank-sort the 16 centers (lanes 0..15 of warp 0) ----
    if (tid < 16) {
        float ci = center[tid];
        int rank = 0;
        #pragma unroll
        for (int j = 0; j < 16; j++) {
            float cj = __shfl_sync(0xffffu, ci, j);
            rank += (cj < ci || (cj == ci && j < tid)) ? 1 : 0;
        }
        s_c[rank]  = ci;
        s_oi[rank] = tid;
    }
    __syncthreads();

    // ---- prep 2: grid params + exact fp32 crossovers (parallel bisection) ----
    if (tid == 0) {
        float mid0  = 0.5f * (s_c[0]  + s_c[1]);
        float mid14 = 0.5f * (s_c[14] + s_c[15]);
        float span  = mid14 - mid0;
        if (!(span > 0.0f)) span = 1e-6f;
        float step = span / (float)(LUT_N - 160);   // 80-cell margins
        float lo   = mid0 - 80.0f * step;
        s_scale = 1.0f / step;
        s_bias  = -lo / step;
    }
    if (tid < 16) {
        float cv;
        if (tid < 15) {
            // exact fp32 flip point of the reference's argmin decision for
            // sorted pair (k,k+1): bracket [c_k, c_{k+1}], monotone predicate,
            // bisect until adjacent floats. cv = smallest x picking RIGHT.
            float cl = s_c[tid], cr = s_c[tid + 1];
            int   ol = s_oi[tid], orr = s_oi[tid + 1];
            float a = cl, b = cr;
            for (int it = 0; it < 60; it++) {
                float m = 0.5f * (a + b);
                if (m <= a || m >= b) break;
                float dl = fabsf(m - cl), dr = fabsf(m - cr);
                bool pl = (dl < dr) || (dl == dr && ol < orr);
                if (pl) a = m; else b = m;
            }
            cv = b;
        } else {
            cv = __int_as_float(0x7f800000);  // +inf sentinel
        }
        s_cross[tid] = cv;
    }
    __syncthreads();

    // ---- prep 3: fill value LUT (NaN marks ambiguous cells) ----
    const float scale = s_scale, bias = s_bias;
    const float inv  = 1.0f / scale;
    const float QNAN = __int_as_float(0x7fc00000);
    for (int i = tid; i < LUT_N; i += 1024) {
        // conservative x-window of code i (rn 0.5 + fma rounding + margin)
        float xlo = ((float)i - 1.5f - bias) * inv;
        float xhi = ((float)i + 1.5f - bias) * inv;
        int below = 0, inwin = 0;
        #pragma unroll
        for (int k = 0; k < 15; k++) {
            float ck = s_cross[k];
            below += (ck < xlo) ? 1 : 0;
            inwin += (ck >= xlo && ck <= xhi) ? 1 : 0;
        }
        s_lut[i] = inwin ? QNAN : s_c[below];
    }
    __syncthreads();

    // ---- main loop: grid-stride, 2x float4, per-thread (no warp collectives) ----
    const int stride = gridDim.x * blockDim.x;
    int i = blockIdx.x * blockDim.x + tid;

    for (; i + stride < n4; i += 2 * stride) {
        float4 a = x[i];
        float4 b = x[i + stride];

        float4 ra, rb;
        ra.x = s_lut[qcode(a.x, scale, bias)];
        ra.y = s_lut[qcode(a.y, scale, bias)];
        ra.z = s_lut[qcode(a.z, scale, bias)];
        ra.w = s_lut[qcode(a.w, scale, bias)];
        rb.x = s_lut[qcode(b.x, scale, bias)];
        rb.y = s_lut[qcode(b.y, scale, bias)];
        rb.z = s_lut[qcode(b.z, scale, bias)];
        rb.w = s_lut[qcode(b.w, scale, bias)];

        // one NaN probe per float4 (NaN propagates through the sum)
        float pa = (ra.x + ra.y) + (ra.z + ra.w);
        float pb = (rb.x + rb.y) + (rb.z + rb.w);
        if (!(pa == pa)) {   // rare per-lane fixup, shuffle-free
            #pragma unroll
            for (int e = 0; e < 4; e++) {
                float xv = (&a.x)[e];
                int r = 0;
                #pragma unroll
                for (int k = 0; k < 15; k++) r += (s_cross[k] <= xv) ? 1 : 0;
                (&ra.x)[e] = s_c[r];
            }
        }
        if (!(pb == pb)) {
            #pragma unroll
            for (int e = 0; e < 4; e++) {
                float xv = (&b.x)[e];
                int r = 0;
                #pragma unroll
                for (int k = 0; k < 15; k++) r += (s_cross[k] <= xv) ? 1 : 0;
                (&rb.x)[e] = s_c[r];
            }
        }

        out[i]          = ra;
        out[i + stride] = rb;
    }
    for (; i < n4; i += stride) {
        float4 a = x[i];
        float4 r;
        r.x = s_lut[qcode(a.x, scale, bias)];
        r.y = s_lut[qcode(a.y, scale, bias)];
        r.z = s_lut[qcode(a.z, scale, bias)];
        r.w = s_lut[qcode(a.w, scale, bias)];
        float p = (r.x + r.y) + (r.z + r.w);
        if (!(p == p)) {
            #pragma unroll
            for (int e = 0; e < 4; e++) {
                float xv = (&a.x)[e];
                int rr = 0;
                #pragma unroll
                for (int k = 0; k < 15; k++) rr += (s_cross[k] <= xv) ? 1 : 0;
                (&r.x)[e] = s_c[rr];
            }
        }
        out[i] = r;
    }
}

// ---------------------------------------------------------------------------
extern "C" void kernel_launch(void* const* d_in, const int* in_sizes, int n_in,
                              void* d_out, int out_size)
{
    const float* x      = (const float*)d_in[0];
    const float* center = (const float*)d_in[1];
    float*       out    = (float*)d_out;
    (void)n_in; (void)out_size;

    const int n  = in_sizes[0];
    const int n4 = n >> 2;

    const int threads = 1024;
    const int blocks  = 296;   // 2 CTAs/SM x 148 SMs
    quant_fused_kernel<<<blocks, threads>>>(
        (const float4*)x, center, (float4*)out, n4);
}

// round 8
// speedup vs baseline: 2.5566x; 1.4184x over previous
#include <cuda_runtime.h>
#include <cuda_bf16.h>
#include <math.h>

// ============================================================================
// quantizer: out = center[argmin_m |x - center[m]|]  (== W_hard; reference's
// (W_hard - W_soft) + W_soft == W_hard up to 1 ulp).
//
// R7 = R2's proven exact branch-free main loop, fused with in-kernel prep.
//   prep (per CTA, ~1us): shuffle rank-sort of 16 centers -> 15 parallel
//     bisections for EXACT fp32 argmin crossovers -> 8K byte-LUT of region-
//     at-lower-edge.
//   main (per element, no branches/votes, exact for every cell):
//     FFMA -> F2I.rn(sat) -> clamp -> LDS.U8 -> SHFL(cross,b) -> cmp ->
//     SHFL(center, b + (x>=thr))
//   4-deep float4 unroll for MLP. Warp-uniform loop bounds keep shuffles
//   full-warp; tail predicates only LDG/STG.
// ============================================================================

#define LUT_SIZE 8192

__device__ __forceinline__ unsigned qcode(float xv, float scale, float bias)
{
    unsigned code = __float2uint_rn(fmaf(xv, scale, bias)); // negatives -> 0
    return umin(code, (unsigned)(LUT_SIZE - 1));
}

__device__ __forceinline__ float qone(float xv, float scale, float bias,
                                      const unsigned char* __restrict__ sblut,
                                      float crossv, float centv)
{
    int b = (int)sblut[qcode(xv, scale, bias)];
    float thr = __shfl_sync(0xffffffffu, crossv, b);
    int r = b + ((xv >= thr) ? 1 : 0);       // r <= 15 (cross[15] = +inf)
    return __shfl_sync(0xffffffffu, centv, r);
}

extern "C" __global__ void __launch_bounds__(1024, 2)
quant_fused_kernel(const float4* __restrict__ x,
                   const float* __restrict__ center,
                   float4* __restrict__ out, int n4)
{
    __shared__ unsigned char sblut[LUT_SIZE];   // 8 KB region-byte LUT
    __shared__ float s_c[16];                   // sorted centers
    __shared__ int   s_oi[16];                  // original idx (argmin tie rule)
    __shared__ float s_cross[16];               // exact crossovers, [15]=+inf
    __shared__ float s_scale, s_bias;

    const int tid  = threadIdx.x;
    const int lane = tid & 31;

    // ---- prep 1: rank-sort 16 centers (lanes 0..15 of warp 0) ----
    if (tid < 16) {
        float ci = center[tid];
        int rank = 0;
        #pragma unroll
        for (int j = 0; j < 16; j++) {
            float cj = __shfl_sync(0xffffu, ci, j);
            rank += (cj < ci || (cj == ci && j < tid)) ? 1 : 0;
        }
        s_c[rank]  = ci;
        s_oi[rank] = tid;
    }
    __syncthreads();

    // ---- prep 2: grid params + exact crossovers (15 parallel bisections) ----
    if (tid == 0) {
        float mid0  = 0.5f * (s_c[0]  + s_c[1]);
        float mid14 = 0.5f * (s_c[14] + s_c[15]);
        float span  = mid14 - mid0;
        if (!(span > 0.0f)) span = 1e-6f;
        float step = span / (float)(LUT_SIZE - 160);   // 80-cell margins
        float lo   = mid0 - 80.0f * step;
        s_scale = 1.0f / step;
        s_bias  = -lo / step;
    }
    if (tid < 16) {
        float cv;
        if (tid < 15) {
            // exact fp32 flip point of the reference's argmin decision for
            // sorted pair (k,k+1): bracket [c_k, c_{k+1}], monotone predicate,
            // bisect to adjacent floats. cv = smallest x picking RIGHT center.
            float cl = s_c[tid], cr = s_c[tid + 1];
            int   ol = s_oi[tid], orr = s_oi[tid + 1];
            float a = cl, b = cr;
            for (int it = 0; it < 60; it++) {
                float m = 0.5f * (a + b);
                if (m <= a || m >= b) break;
                float dl = fabsf(m - cl), dr = fabsf(m - cr);
                bool pl = (dl < dr) || (dl == dr && ol < orr);
                if (pl) a = m; else b = m;
            }
            cv = b;
        } else {
            cv = __int_as_float(0x7f800000);  // +inf sentinel for region 15
        }
        s_cross[tid] = cv;
    }
    __syncthreads();

    // ---- prep 3: fill byte LUT (region index at the cell's lower edge) ----
    const float scale = s_scale, bias = s_bias;
    const float inv = 1.0f / scale;
    for (int i = tid; i < LUT_SIZE; i += 1024) {
        // conservative lower x-edge of code i (rn 0.5 + fma rounding margin)
        float xlo = ((float)i - 1.5f - bias) * inv;
        int b = 0;
        #pragma unroll
        for (int k = 0; k < 15; k++) b += (s_cross[k] <= xlo) ? 1 : 0;
        sblut[i] = (unsigned char)b;
    }

    const float crossv = s_cross[lane & 15];   // per-lane register tables
    const float centv  = s_c[lane & 15];
    __syncthreads();

    // ---- main loop: warp-uniform bounds, 4x float4 deep ----
    const int stride = gridDim.x * blockDim.x;
    int i  = blockIdx.x * blockDim.x + tid;
    int wb = i - lane;                          // warp-uniform base index

    for (; wb + 31 + 3 * stride < n4; i += 4 * stride, wb += 4 * stride) {
        float4 a = x[i];
        float4 b = x[i + stride];
        float4 c = x[i + 2 * stride];
        float4 d = x[i + 3 * stride];

        float4 ra, rb, rc, rd;
        ra.x = qone(a.x, scale, bias, sblut, crossv, centv);
        ra.y = qone(a.y, scale, bias, sblut, crossv, centv);
        ra.z = qone(a.z, scale, bias, sblut, crossv, centv);
        ra.w = qone(a.w, scale, bias, sblut, crossv, centv);
        rb.x = qone(b.x, scale, bias, sblut, crossv, centv);
        rb.y = qone(b.y, scale, bias, sblut, crossv, centv);
        rb.z = qone(b.z, scale, bias, sblut, crossv, centv);
        rb.w = qone(b.w, scale, bias, sblut, crossv, centv);
        rc.x = qone(c.x, scale, bias, sblut, crossv, centv);
        rc.y = qone(c.y, scale, bias, sblut, crossv, centv);
        rc.z = qone(c.z, scale, bias, sblut, crossv, centv);
        rc.w = qone(c.w, scale, bias, sblut, crossv, centv);
        rd.x = qone(d.x, scale, bias, sblut, crossv, centv);
        rd.y = qone(d.y, scale, bias, sblut, crossv, centv);
        rd.z = qone(d.z, scale, bias, sblut, crossv, centv);
        rd.w = qone(d.w, scale, bias, sblut, crossv, centv);

        out[i]              = ra;
        out[i + stride]     = rb;
        out[i + 2 * stride] = rc;
        out[i + 3 * stride] = rd;
    }
    // tail: full-warp shuffles, predicated LDG/STG only
    for (; wb < n4; i += stride, wb += stride) {
        const bool v = (i < n4);
        float4 a = v ? x[i] : make_float4(0.f, 0.f, 0.f, 0.f);
        float4 r;
        r.x = qone(a.x, scale, bias, sblut, crossv, centv);
        r.y = qone(a.y, scale, bias, sblut, crossv, centv);
        r.z = qone(a.z, scale, bias, sblut, crossv, centv);
        r.w = qone(a.w, scale, bias, sblut, crossv, centv);
        if (v) out[i] = r;
    }
}

// ---------------------------------------------------------------------------
extern "C" void kernel_launch(void* const* d_in, const int* in_sizes, int n_in,
                              void* d_out, int out_size)
{
    const float* x      = (const float*)d_in[0];
    const float* center = (const float*)d_in[1];
    float*       out    = (float*)d_out;
    (void)n_in; (void)out_size;

    const int n  = in_sizes[0];
    const int n4 = n >> 2;

    const int threads = 1024;
    const int blocks  = 296;   // 2 CTAs/SM x 148 SMs
    quant_fused_kernel<<<blocks, threads>>>(
        (const float4*)x, center, (float4*)out, n4);
}

// round 9
// speedup vs baseline: 2.8708x; 1.1229x over previous
#include <cuda_runtime.h>
#include <cuda_bf16.h>
#include <math.h>

// ============================================================================
// quantizer: out = center[argmin_m |x - center[m]|]  (== W_hard; reference's
// (W_hard - W_soft) + W_soft == W_hard up to 1 ulp).
//
// R9 = fused prep + R2's exact branch-free main loop at 2-deep unroll
// (the measured-fastest body: 16 live floats fits the 32-reg cap of
// __launch_bounds__(1024,2); 4-deep spills — R1/R7 both measured 31.4us,
// 2-deep measured 22.9us).
//   prep (per CTA, ~1-2us): shuffle rank-sort of 16 centers -> 15 parallel
//     bisections for EXACT fp32 argmin crossovers -> 8K byte-LUT.
//   main per element: FFMA -> F2I.rn(sat) -> clamp -> LDS.U8 ->
//     SHFL(cross,b) -> cmp -> SHFL(center, b+(x>=thr)).  No branches/votes.
// ============================================================================

#define LUT_SIZE 8192

__device__ __forceinline__ unsigned qcode(float xv, float scale, float bias)
{
    unsigned code = __float2uint_rn(fmaf(xv, scale, bias)); // negatives -> 0
    return umin(code, (unsigned)(LUT_SIZE - 1));
}

__device__ __forceinline__ float qone(float xv, float scale, float bias,
                                      const unsigned char* __restrict__ sblut,
                                      float crossv, float centv)
{
    int b = (int)sblut[qcode(xv, scale, bias)];
    float thr = __shfl_sync(0xffffffffu, crossv, b);
    int r = b + ((xv >= thr) ? 1 : 0);       // r <= 15 (cross[15] = +inf)
    return __shfl_sync(0xffffffffu, centv, r);
}

extern "C" __global__ void __launch_bounds__(1024, 2)
quant_fused_kernel(const float4* __restrict__ x,
                   const float* __restrict__ center,
                   float4* __restrict__ out, int n4)
{
    __shared__ unsigned char sblut[LUT_SIZE];   // 8 KB region-byte LUT
    __shared__ float s_c[16];                   // sorted centers
    __shared__ int   s_oi[16];                  // original idx (argmin tie rule)
    __shared__ float s_cross[16];               // exact crossovers, [15]=+inf
    __shared__ float s_scale, s_bias;

    const int tid  = threadIdx.x;
    const int lane = tid & 31;

    // ---- prep 1: rank-sort 16 centers (lanes 0..15 of warp 0) ----
    if (tid < 16) {
        float ci = center[tid];
        int rank = 0;
        #pragma unroll
        for (int j = 0; j < 16; j++) {
            float cj = __shfl_sync(0xffffu, ci, j);
            rank += (cj < ci || (cj == ci && j < tid)) ? 1 : 0;
        }
        s_c[rank]  = ci;
        s_oi[rank] = tid;
    }
    __syncthreads();

    // ---- prep 2: grid params + exact crossovers (15 parallel bisections) ----
    if (tid == 0) {
        float mid0  = 0.5f * (s_c[0]  + s_c[1]);
        float mid14 = 0.5f * (s_c[14] + s_c[15]);
        float span  = mid14 - mid0;
        if (!(span > 0.0f)) span = 1e-6f;
        float step = span / (float)(LUT_SIZE - 160);   // 80-cell margins
        float lo   = mid0 - 80.0f * step;
        s_scale = 1.0f / step;
        s_bias  = -lo / step;
    }
    if (tid < 16) {
        float cv;
        if (tid < 15) {
            // exact fp32 flip point of the reference's argmin decision for
            // sorted pair (k,k+1): bracket [c_k, c_{k+1}], monotone predicate,
            // bisect to adjacent floats. cv = smallest x picking RIGHT center.
            float cl = s_c[tid], cr = s_c[tid + 1];
            int   ol = s_oi[tid], orr = s_oi[tid + 1];
            float a = cl, b = cr;
            for (int it = 0; it < 60; it++) {
                float m = 0.5f * (a + b);
                if (m <= a || m >= b) break;
                float dl = fabsf(m - cl), dr = fabsf(m - cr);
                bool pl = (dl < dr) || (dl == dr && ol < orr);
                if (pl) a = m; else b = m;
            }
            cv = b;
        } else {
            cv = __int_as_float(0x7f800000);  // +inf sentinel for region 15
        }
        s_cross[tid] = cv;
    }
    __syncthreads();

    // ---- prep 3: fill byte LUT (region index at the cell's lower edge) ----
    const float scale = s_scale, bias = s_bias;
    const float inv = 1.0f / scale;
    for (int i = tid; i < LUT_SIZE; i += 1024) {
        // conservative lower x-edge of code i (rn 0.5 + fma rounding margin)
        float xlo = ((float)i - 1.5f - bias) * inv;
        int b = 0;
        #pragma unroll
        for (int k = 0; k < 15; k++) b += (s_cross[k] <= xlo) ? 1 : 0;
        sblut[i] = (unsigned char)b;
    }

    const float crossv = s_cross[lane & 15];   // per-lane register tables
    const float centv  = s_c[lane & 15];
    __syncthreads();

    // ---- main loop: warp-uniform bounds, 2x float4 deep (fits 32 regs) ----
    const int stride = gridDim.x * blockDim.x;
    int i  = blockIdx.x * blockDim.x + tid;
    int wb = i - lane;                          // warp-uniform base index

    for (; wb + 31 + stride < n4; i += 2 * stride, wb += 2 * stride) {
        float4 a = x[i];
        float4 b = x[i + stride];
        float4 ra, rb;
        ra.x = qone(a.x, scale, bias, sblut, crossv, centv);
        ra.y = qone(a.y, scale, bias, sblut, crossv, centv);
        ra.z = qone(a.z, scale, bias, sblut, crossv, centv);
        ra.w = qone(a.w, scale, bias, sblut, crossv, centv);
        rb.x = qone(b.x, scale, bias, sblut, crossv, centv);
        rb.y = qone(b.y, scale, bias, sblut, crossv, centv);
        rb.z = qone(b.z, scale, bias, sblut, crossv, centv);
        rb.w = qone(b.w, scale, bias, sblut, crossv, centv);
        out[i]          = ra;
        out[i + stride] = rb;
    }
    // tail: full-warp shuffles, predicated LDG/STG only
    for (; wb < n4; i += stride, wb += stride) {
        const bool v = (i < n4);
        float4 a = v ? x[i] : make_float4(0.f, 0.f, 0.f, 0.f);
        float4 r;
        r.x = qone(a.x, scale, bias, sblut, crossv, centv);
        r.y = qone(a.y, scale, bias, sblut, crossv, centv);
        r.z = qone(a.z, scale, bias, sblut, crossv, centv);
        r.w = qone(a.w, scale, bias, sblut, crossv, centv);
        if (v) out[i] = r;
    }
}

// ---------------------------------------------------------------------------
extern "C" void kernel_launch(void* const* d_in, const int* in_sizes, int n_in,
                              void* d_out, int out_size)
{
    const float* x      = (const float*)d_in[0];
    const float* center = (const float*)d_in[1];
    float*       out    = (float*)d_out;
    (void)n_in; (void)out_size;

    const int n  = in_sizes[0];
    const int n4 = n >> 2;

    const int threads = 1024;
    const int blocks  = 296;   // 2 CTAs/SM x 148 SMs
    quant_fused_kernel<<<blocks, threads>>>(
        (const float4*)x, center, (float4*)out, n4);
}